// round 6
// baseline (speedup 1.0000x reference)
#include <cuda_runtime.h>
#include <cstdint>

#define NSEQ 8
#define QLEN 128
#define NQH 32
#define NKVH 8
#define GQA 4
#define HD 128
#define BLKSZ 16
#define MAXBLK 128
#define LTOT 2048
#define NSEG 4
#define TILEC 32

#define NCT 64            // tokens per chunk
#define MROWS 64          // q rows per CTA
#define NTHREADS 128      // 4 warps x m16

// smem strides (floats): chosen so stride mod 32 = 4 -> conflict-free fragment access
#define QST 132
#define KST 68
#define VST 132
#define PST 68            // P overlays K buffer (same stride constraint: 68)

// smem float offsets
#define OFF_QHI 0
#define OFF_QLO (OFF_QHI + MROWS*QST)          // 8448
#define OFF_KHI (OFF_QLO + MROWS*QST)          // 16896
#define OFF_KLO (OFF_KHI + HD*KST)             // +8704
#define OFF_VHI (OFF_KLO + HD*KST)
#define OFF_VLO (OFF_VHI + NCT*VST)
#define SMEM_FLOATS (OFF_VLO + NCT*VST)
#define SMEM_BYTES (SMEM_FLOATS*4)

static __device__ __forceinline__ void mma_tf32(float c[4], const uint32_t a[4],
                                                uint32_t b0, uint32_t b1) {
    asm volatile(
        "mma.sync.aligned.m16n8k8.row.col.f32.tf32.tf32.f32 "
        "{%0,%1,%2,%3}, {%4,%5,%6,%7}, {%8,%9}, {%0,%1,%2,%3};"
        : "+f"(c[0]), "+f"(c[1]), "+f"(c[2]), "+f"(c[3])
        : "r"(a[0]), "r"(a[1]), "r"(a[2]), "r"(a[3]), "r"(b0), "r"(b1));
}

static __device__ __forceinline__ void tf32_split(float x, float& hi, float& lo) {
    uint32_t h;
    asm("cvt.rna.tf32.f32 %0, %1;" : "=r"(h) : "f"(x));
    hi = __uint_as_float(h);
    float lf = x - hi;
    uint32_t l;
    asm("cvt.rna.tf32.f32 %0, %1;" : "=r"(l) : "f"(lf));
    lo = __uint_as_float(l);
}

static __device__ __forceinline__ uint32_t f2u(float x) { return __float_as_uint(x); }

__global__ void __launch_bounds__(NTHREADS, 1)
paged_seg_attn_mma(const float* __restrict__ q,
                   const float* __restrict__ kc,
                   const float* __restrict__ vc,
                   const int*   __restrict__ bt,
                   const int*   __restrict__ seqlens,
                   const float* __restrict__ scale_p,
                   const float* __restrict__ softcap_p,
                   float*       __restrict__ out)
{
    extern __shared__ float sm[];
    float* Qhi = sm + OFF_QHI;
    float* Qlo = sm + OFF_QLO;
    float* Khi = sm + OFF_KHI;   // reused as Phi after QK
    float* Klo = sm + OFF_KLO;   // reused as Plo
    float* Vhi = sm + OFF_VHI;
    float* Vlo = sm + OFF_VLO;

    const int bx  = blockIdx.x;          // 0..7: seg*2 + qhalf
    const int seg = bx >> 1;
    const int qh  = bx & 1;
    const int g   = blockIdx.y;          // GQA sub-head
    const int z   = blockIdx.z;
    const int s   = z >> 3;
    const int kv  = z & 7;
    const int h   = kv * GQA + g;

    const int tid  = threadIdx.x;
    const int w    = tid >> 5;           // warp 0..3: rows w*16..w*16+15
    const int lane = tid & 31;
    const int gid  = lane >> 2;          // 0..7
    const int tig  = lane & 3;           // 0..3
    const int qb   = w * 16;

    const float scale = *scale_p;
    const float cap   = *softcap_p;
    const float tcoef = (cap > 0.f) ? (2.0f * scale / cap) : 0.f;
    const float n2cap = -2.0f * cap;

    const int seq_len   = seqlens[s];
    const int ctx       = seq_len - QLEN;
    const int span      = ((seq_len + NSEG * TILEC - 1) / (NSEG * TILEC)) * TILEC;
    const int seg_start = seg * span;
    const int seg_end   = min(seg_start + span, LTOT);

    const int  qrow0 = qh * 64 + qb + gid;         // CTA-relative q row (within 128)
    const int  kmax0 = ctx + qrow0;
    const int  kmax1 = kmax0 + 8;

    const int* btrow = bt + s * MAXBLK;

    // ---- stage Q (hi/lo tf32 split): rows 0..63 of this half ----
    {
        #pragma unroll
        for (int it = 0; it < 16; it++) {
            int i  = tid + it * NTHREADS;          // 0..2047
            int r  = i >> 5;                       // 0..63
            int d4 = (i & 31) * 4;
            const float* src = q + ((size_t)(s * QLEN + qh * 64 + r) * NQH + h) * HD + d4;
            float4 v = *(const float4*)src;
            float hx, lx;
            tf32_split(v.x, hx, lx); Qhi[r*QST + d4+0] = hx; Qlo[r*QST + d4+0] = lx;
            tf32_split(v.y, hx, lx); Qhi[r*QST + d4+1] = hx; Qlo[r*QST + d4+1] = lx;
            tf32_split(v.z, hx, lx); Qhi[r*QST + d4+2] = hx; Qlo[r*QST + d4+2] = lx;
            tf32_split(v.w, hx, lx); Qhi[r*QST + d4+3] = hx; Qlo[r*QST + d4+3] = lx;
        }
    }

    float o[16][4];
    #pragma unroll
    for (int a = 0; a < 16; a++)
        #pragma unroll
        for (int b = 0; b < 4; b++) o[a][b] = 0.f;

    float pmax0 = 0.f, pmax1 = 0.f;

    for (int base = seg_start; base < seg_end; base += NCT) {
        __syncthreads();   // prev chunk's PV done: K(P)/V buffers free

        // ---- K chunk -> Khi/Klo[d][tok] ----
        #pragma unroll
        for (int it = 0; it < 16; it++) {
            int i   = tid + it * NTHREADS;   // 0..2047
            int d   = i >> 4;
            int r   = i & 15;
            int blk = r >> 2;
            int t4  = (r & 3) * 4;
            int pb  = btrow[(base >> 4) + blk];
            float4 v = *(const float4*)(kc + (((size_t)pb * NKVH + kv) * HD + d) * BLKSZ + t4);
            int t0 = blk * BLKSZ + t4;
            float hx, lx;
            tf32_split(v.x, hx, lx); Khi[d*KST + t0+0] = hx; Klo[d*KST + t0+0] = lx;
            tf32_split(v.y, hx, lx); Khi[d*KST + t0+1] = hx; Klo[d*KST + t0+1] = lx;
            tf32_split(v.z, hx, lx); Khi[d*KST + t0+2] = hx; Klo[d*KST + t0+2] = lx;
            tf32_split(v.w, hx, lx); Khi[d*KST + t0+3] = hx; Klo[d*KST + t0+3] = lx;
        }
        // ---- V chunk -> Vhi/Vlo[tok][d] (transposed) ----
        #pragma unroll
        for (int it = 0; it < 16; it++) {
            int i   = tid + it * NTHREADS;
            int d   = i >> 4;
            int r   = i & 15;
            int blk = r >> 2;
            int t4  = (r & 3) * 4;
            int pb  = btrow[(base >> 4) + blk];
            float4 v = *(const float4*)(vc + (((size_t)pb * NKVH + kv) * HD + d) * BLKSZ + t4);
            int t0 = blk * BLKSZ + t4;
            float hx, lx;
            tf32_split(v.x, hx, lx); Vhi[(t0+0)*VST + d] = hx; Vlo[(t0+0)*VST + d] = lx;
            tf32_split(v.y, hx, lx); Vhi[(t0+1)*VST + d] = hx; Vlo[(t0+1)*VST + d] = lx;
            tf32_split(v.z, hx, lx); Vhi[(t0+2)*VST + d] = hx; Vlo[(t0+2)*VST + d] = lx;
            tf32_split(v.w, hx, lx); Vhi[(t0+3)*VST + d] = hx; Vlo[(t0+3)*VST + d] = lx;
        }
        __syncthreads();

        // ---- QK: S[16q x 64tok] per warp ----
        float sacc[8][4];
        #pragma unroll
        for (int a = 0; a < 8; a++)
            #pragma unroll
            for (int b = 0; b < 4; b++) sacc[a][b] = 0.f;

        #pragma unroll 4
        for (int ks = 0; ks < 16; ks++) {
            int dk = ks * 8 + tig;
            uint32_t ah[4], al[4];
            ah[0] = f2u(Qhi[(qb+gid  )*QST + dk  ]);
            ah[1] = f2u(Qhi[(qb+gid+8)*QST + dk  ]);
            ah[2] = f2u(Qhi[(qb+gid  )*QST + dk+4]);
            ah[3] = f2u(Qhi[(qb+gid+8)*QST + dk+4]);
            al[0] = f2u(Qlo[(qb+gid  )*QST + dk  ]);
            al[1] = f2u(Qlo[(qb+gid+8)*QST + dk  ]);
            al[2] = f2u(Qlo[(qb+gid  )*QST + dk+4]);
            al[3] = f2u(Qlo[(qb+gid+8)*QST + dk+4]);
            #pragma unroll
            for (int nt = 0; nt < 8; nt++) {
                int tn = nt * 8 + gid;
                uint32_t bh0 = f2u(Khi[(dk  )*KST + tn]);
                uint32_t bh1 = f2u(Khi[(dk+4)*KST + tn]);
                uint32_t bl0 = f2u(Klo[(dk  )*KST + tn]);
                uint32_t bl1 = f2u(Klo[(dk+4)*KST + tn]);
                mma_tf32(sacc[nt], ah, bh0, bh1);
                mma_tf32(sacc[nt], al, bh0, bh1);
                mma_tf32(sacc[nt], ah, bl0, bl1);
            }
        }

        // ---- softcap + mask + p = exp(v - cap) ----
        float phv[8][4], plv[8][4];
        #pragma unroll
        for (int nt = 0; nt < 8; nt++) {
            int t0 = base + nt * 8 + 2 * tig;
            int t1 = t0 + 1;
            #pragma unroll
            for (int e = 0; e < 4; e++) {
                int tpos = (e & 1) ? t1 : t0;
                int kmax = (e < 2) ? kmax0 : kmax1;
                float raw = sacc[nt][e];
                float ex  = __expf(raw * tcoef);
                float p   = __expf(__fdividef(n2cap, ex + 1.f));  // exp(v - cap)
                bool ok   = (tpos <= kmax) && (tpos < seg_end);
                p = ok ? p : 0.f;
                if (e < 2) pmax0 = fmaxf(pmax0, p); else pmax1 = fmaxf(pmax1, p);
                float hx, lx;
                tf32_split(p, hx, lx);
                phv[nt][e] = hx;
                plv[nt][e] = lx;
            }
        }

        __syncthreads();   // all warps done reading K -> safe to overwrite with P

        // ---- store P into K buffer: Phi/Plo[row(0..63)][tok], float2 stores ----
        #pragma unroll
        for (int nt = 0; nt < 8; nt++) {
            int tloc = nt * 8 + 2 * tig;
            *(float2*)(Khi + (qb+gid  )*PST + tloc) = make_float2(phv[nt][0], phv[nt][1]);
            *(float2*)(Khi + (qb+gid+8)*PST + tloc) = make_float2(phv[nt][2], phv[nt][3]);
            *(float2*)(Klo + (qb+gid  )*PST + tloc) = make_float2(plv[nt][0], plv[nt][1]);
            *(float2*)(Klo + (qb+gid+8)*PST + tloc) = make_float2(plv[nt][2], plv[nt][3]);
        }
        __syncwarp();      // warp reads only its own P rows -> warp-local ordering suffices

        // ---- PV: O[16q x 128d] += P * V ----
        #pragma unroll 2
        for (int ks = 0; ks < 8; ks++) {
            int tk = ks * 8 + tig;
            uint32_t ah[4], al[4];
            ah[0] = f2u(Khi[(qb+gid  )*PST + tk  ]);
            ah[1] = f2u(Khi[(qb+gid+8)*PST + tk  ]);
            ah[2] = f2u(Khi[(qb+gid  )*PST + tk+4]);
            ah[3] = f2u(Khi[(qb+gid+8)*PST + tk+4]);
            al[0] = f2u(Klo[(qb+gid  )*PST + tk  ]);
            al[1] = f2u(Klo[(qb+gid+8)*PST + tk  ]);
            al[2] = f2u(Klo[(qb+gid  )*PST + tk+4]);
            al[3] = f2u(Klo[(qb+gid+8)*PST + tk+4]);
            #pragma unroll
            for (int nt = 0; nt < 16; nt++) {
                int dn = nt * 8 + gid;
                uint32_t bh0 = f2u(Vhi[(tk  )*VST + dn]);
                uint32_t bh1 = f2u(Vhi[(tk+4)*VST + dn]);
                uint32_t bl0 = f2u(Vlo[(tk  )*VST + dn]);
                uint32_t bl1 = f2u(Vlo[(tk+4)*VST + dn]);
                mma_tf32(o[nt], ah, bh0, bh1);
                mma_tf32(o[nt], al, bh0, bh1);
                mma_tf32(o[nt], ah, bl0, bl1);
            }
        }
    }

    // ---- epilogue: row max reduce (4 lanes per row: xor 1,2), scale, store ----
    #pragma unroll
    for (int off = 1; off < 4; off <<= 1) {
        pmax0 = fmaxf(pmax0, __shfl_xor_sync(0xffffffffu, pmax0, off));
        pmax1 = fmaxf(pmax1, __shfl_xor_sync(0xffffffffu, pmax1, off));
    }
    const float f0 = (pmax0 > 0.f) ? (1.0f / pmax0) : 0.f;
    const float f1 = (pmax1 > 0.f) ? (1.0f / pmax1) : 0.f;

    const int trow0 = s * QLEN + qh * 64 + qb + gid;
    float* o0 = out + (((size_t)trow0       * NQH + h) * NSEG + seg) * (size_t)HD;
    float* o1 = out + (((size_t)(trow0 + 8) * NQH + h) * NSEG + seg) * (size_t)HD;
    #pragma unroll
    for (int nt = 0; nt < 16; nt++) {
        int d0 = nt * 8 + 2 * tig;
        *(float2*)(o0 + d0) = make_float2(o[nt][0] * f0, o[nt][1] * f0);
        *(float2*)(o1 + d0) = make_float2(o[nt][2] * f1, o[nt][3] * f1);
    }
}

extern "C" void kernel_launch(void* const* d_in, const int* in_sizes, int n_in,
                              void* d_out, int out_size) {
    const float* q   = (const float*)d_in[0];
    const float* kc  = (const float*)d_in[1];
    const float* vc  = (const float*)d_in[2];
    const int*   bt  = (const int*)d_in[3];
    const int*   sl  = (const int*)d_in[4];
    const float* sc  = (const float*)d_in[6];
    const float* cap = (const float*)d_in[9];
    float* out = (float*)d_out;

    static int init_done = 0;
    if (!init_done) {
        cudaFuncSetAttribute(paged_seg_attn_mma,
                             cudaFuncAttributeMaxDynamicSharedMemorySize, SMEM_BYTES);
        init_done = 1;
    }
    dim3 grid(NSEG * 2, GQA, NSEQ * NKVH);
    paged_seg_attn_mma<<<grid, NTHREADS, SMEM_BYTES>>>(q, kc, vc, bt, sl, sc, cap, out);
}

// round 7
// speedup vs baseline: 1.2661x; 1.2661x over previous
#include <cuda_runtime.h>
#include <cstdint>

#define NSEQ 8
#define QLEN 128
#define NQH 32
#define NKVH 8
#define GQA 4
#define HD 128
#define BLKSZ 16
#define MAXBLK 128
#define LTOT 2048
#define NSEG 4
#define TILEC 32

#define NCT 64
#define NTHREADS 256

// strides in float2 units (mod 16 == 4 -> conflict-free fragment access)
#define QS2 132
#define KS2 132            // K2 / V2: [tok][d]
#define PS2 68             // P overlays K2

// smem offsets in float2 units
#define OFF_Q2 0
#define OFF_K2 (OFF_Q2 + 64*QS2)
#define OFF_V2 (OFF_K2 + NCT*KS2)
#define OFF_PM (OFF_V2 + NCT*KS2)
#define SMEM_F2 (OFF_PM + 64)
#define SMEM_BYTES (SMEM_F2*8)

static __device__ __forceinline__ void mma_tf32(float c[4], const uint32_t a[4],
                                                uint32_t b0, uint32_t b1) {
    asm volatile(
        "mma.sync.aligned.m16n8k8.row.col.f32.tf32.tf32.f32 "
        "{%0,%1,%2,%3}, {%4,%5,%6,%7}, {%8,%9}, {%0,%1,%2,%3};"
        : "+f"(c[0]), "+f"(c[1]), "+f"(c[2]), "+f"(c[3])
        : "r"(a[0]), "r"(a[1]), "r"(a[2]), "r"(a[3]), "r"(b0), "r"(b1));
}

static __device__ __forceinline__ float2 tf32_split2(float x) {
    uint32_t h;
    asm("cvt.rna.tf32.f32 %0, %1;" : "=r"(h) : "f"(x));
    float hi = __uint_as_float(h);
    float lf = x - hi;
    uint32_t l;
    asm("cvt.rna.tf32.f32 %0, %1;" : "=r"(l) : "f"(lf));
    return make_float2(hi, __uint_as_float(l));
}

static __device__ __forceinline__ uint32_t f2u(float x) { return __float_as_uint(x); }

__global__ void __launch_bounds__(NTHREADS, 1)
paged_seg_attn_mma8(const float* __restrict__ q,
                    const float* __restrict__ kc,
                    const float* __restrict__ vc,
                    const int*   __restrict__ bt,
                    const int*   __restrict__ seqlens,
                    const float* __restrict__ scale_p,
                    const float* __restrict__ softcap_p,
                    float*       __restrict__ out)
{
    extern __shared__ float2 sm2[];
    float2* Q2 = sm2 + OFF_Q2;
    float2* K2 = sm2 + OFF_K2;       // K tile [tok][d]; reused as P2 [row][tok]
    float2* V2 = sm2 + OFF_V2;       // V tile [tok][d]
    float2* P2 = K2;
    float*  PM = (float*)(sm2 + OFF_PM);   // [2][64] partial p-max

    const int bx  = blockIdx.x;      // seg*2 + qhalf
    const int seg = bx >> 1;
    const int qh  = bx & 1;
    const int g   = blockIdx.y;
    const int z   = blockIdx.z;
    const int s   = z >> 3;
    const int kv  = z & 7;
    const int h   = kv * GQA + g;

    const int tid  = threadIdx.x;
    const int w    = tid >> 5;
    const int wq   = w >> 1;         // 0..3: q rows wq*16..+15
    const int wh   = w & 1;          // QK: token half; PV: d half
    const int lane = tid & 31;
    const int gid  = lane >> 2;
    const int tig  = lane & 3;
    const int qb   = wq * 16;
    const int th0  = wh * 32;        // QK token offset
    const int dh0  = wh * 64;        // PV d offset

    const float scale = *scale_p;
    const float cap   = *softcap_p;
    const float tcoef = (cap > 0.f) ? (2.0f * scale / cap) : 0.f;
    const float n2cap = -2.0f * cap;

    const int seq_len   = seqlens[s];
    const int ctx       = seq_len - QLEN;
    const int span      = ((seq_len + NSEG * TILEC - 1) / (NSEG * TILEC)) * TILEC;
    const int seg_start = seg * span;
    const int seg_end   = min(seg_start + span, LTOT);

    const int kmax0 = ctx + qh * 64 + qb + gid;
    const int kmax1 = kmax0 + 8;

    const int* btrow = bt + s * MAXBLK;

    // ---- stage Q (hi/lo interleaved float2), once ----
    #pragma unroll
    for (int it = 0; it < 8; it++) {
        int i  = tid + it * NTHREADS;             // 0..2047
        int r  = i >> 5;                          // 0..63
        int d4 = (i & 31) * 4;
        const float* src = q + ((size_t)(s * QLEN + qh * 64 + r) * NQH + h) * HD + d4;
        float4 v = *(const float4*)src;
        Q2[r*QS2 + d4+0] = tf32_split2(v.x);
        Q2[r*QS2 + d4+1] = tf32_split2(v.y);
        Q2[r*QS2 + d4+2] = tf32_split2(v.z);
        Q2[r*QS2 + d4+3] = tf32_split2(v.w);
    }

    float o[8][4];
    #pragma unroll
    for (int a = 0; a < 8; a++)
        #pragma unroll
        for (int b = 0; b < 4; b++) o[a][b] = 0.f;

    float pmax0 = 0.f, pmax1 = 0.f;

    for (int base = seg_start; base < seg_end; base += NCT) {
        __syncthreads();   // prev chunk PV done: K2/P2, V2 free

        // ---- stage K chunk [tok][d] (lanes sweep d -> conflict-free) ----
        #pragma unroll
        for (int it = 0; it < 8; it++) {
            int i   = tid + it * NTHREADS;        // 0..2047
            int d   = i & 127;
            int rr  = i >> 7;                     // 0..15
            int blk = rr >> 2;                    // 0..3
            int t4  = (rr & 3) * 4;
            int kb  = min((base >> 4) + blk, MAXBLK - 1);
            int pb  = btrow[kb];
            float4 v = *(const float4*)(kc + (((size_t)pb * NKVH + kv) * HD + d) * BLKSZ + t4);
            int t0 = blk * BLKSZ + t4;
            K2[(t0+0)*KS2 + d] = tf32_split2(v.x);
            K2[(t0+1)*KS2 + d] = tf32_split2(v.y);
            K2[(t0+2)*KS2 + d] = tf32_split2(v.z);
            K2[(t0+3)*KS2 + d] = tf32_split2(v.w);
        }
        // ---- stage V chunk [tok][d] ----
        #pragma unroll
        for (int it = 0; it < 8; it++) {
            int i   = tid + it * NTHREADS;
            int d   = i & 127;
            int rr  = i >> 7;
            int blk = rr >> 2;
            int t4  = (rr & 3) * 4;
            int kb  = min((base >> 4) + blk, MAXBLK - 1);
            int pb  = btrow[kb];
            float4 v = *(const float4*)(vc + (((size_t)pb * NKVH + kv) * HD + d) * BLKSZ + t4);
            int t0 = blk * BLKSZ + t4;
            V2[(t0+0)*KS2 + d] = tf32_split2(v.x);
            V2[(t0+1)*KS2 + d] = tf32_split2(v.y);
            V2[(t0+2)*KS2 + d] = tf32_split2(v.z);
            V2[(t0+3)*KS2 + d] = tf32_split2(v.w);
        }
        __syncthreads();

        // ---- QK: 16q x 32tok per warp ----
        float sacc[4][4];
        #pragma unroll
        for (int a = 0; a < 4; a++)
            #pragma unroll
            for (int b = 0; b < 4; b++) sacc[a][b] = 0.f;

        #pragma unroll 4
        for (int ks = 0; ks < 16; ks++) {
            int dk = ks * 8 + tig;
            float2 qa0 = Q2[(qb+gid  )*QS2 + dk];
            float2 qa1 = Q2[(qb+gid+8)*QS2 + dk];
            float2 qa2 = Q2[(qb+gid  )*QS2 + dk+4];
            float2 qa3 = Q2[(qb+gid+8)*QS2 + dk+4];
            uint32_t ah[4] = {f2u(qa0.x), f2u(qa1.x), f2u(qa2.x), f2u(qa3.x)};
            uint32_t al[4] = {f2u(qa0.y), f2u(qa1.y), f2u(qa2.y), f2u(qa3.y)};
            #pragma unroll
            for (int nt = 0; nt < 4; nt++) {
                int tn = th0 + nt * 8 + gid;
                float2 b0 = K2[tn*KS2 + dk];
                float2 b1 = K2[tn*KS2 + dk+4];
                mma_tf32(sacc[nt], ah, f2u(b0.x), f2u(b1.x));
                mma_tf32(sacc[nt], al, f2u(b0.x), f2u(b1.x));
                mma_tf32(sacc[nt], ah, f2u(b0.y), f2u(b1.y));
            }
        }

        // ---- softcap + mask + p = exp(v - cap) ----
        float2 pv[4][4];   // split p values
        #pragma unroll
        for (int nt = 0; nt < 4; nt++) {
            #pragma unroll
            for (int e = 0; e < 4; e++) {
                int tpos = base + th0 + nt * 8 + 2 * tig + (e & 1);
                int kmax = (e < 2) ? kmax0 : kmax1;
                float raw = sacc[nt][e];
                float ex  = __expf(raw * tcoef);
                float p   = __expf(__fdividef(n2cap, ex + 1.f));   // exp(v - cap)
                bool ok   = (tpos <= kmax) && (tpos < seg_end);
                p = ok ? p : 0.f;
                if (e < 2) pmax0 = fmaxf(pmax0, p); else pmax1 = fmaxf(pmax1, p);
                pv[nt][e] = tf32_split2(p);
            }
        }

        __syncthreads();   // all warps done reading K2

        // ---- store P [row][tok] into K2 buffer ----
        #pragma unroll
        for (int nt = 0; nt < 4; nt++) {
            int tl = th0 + nt * 8 + 2 * tig;
            P2[(qb+gid  )*PS2 + tl    ] = pv[nt][0];
            P2[(qb+gid  )*PS2 + tl + 1] = pv[nt][1];
            P2[(qb+gid+8)*PS2 + tl    ] = pv[nt][2];
            P2[(qb+gid+8)*PS2 + tl + 1] = pv[nt][3];
        }
        __syncthreads();   // P visible to all warps

        // ---- PV: 16q x 64d per warp ----
        #pragma unroll 2
        for (int ks = 0; ks < 8; ks++) {
            int tk = ks * 8 + tig;
            float2 pa0 = P2[(qb+gid  )*PS2 + tk];
            float2 pa1 = P2[(qb+gid+8)*PS2 + tk];
            float2 pa2 = P2[(qb+gid  )*PS2 + tk+4];
            float2 pa3 = P2[(qb+gid+8)*PS2 + tk+4];
            uint32_t ah[4] = {f2u(pa0.x), f2u(pa1.x), f2u(pa2.x), f2u(pa3.x)};
            uint32_t al[4] = {f2u(pa0.y), f2u(pa1.y), f2u(pa2.y), f2u(pa3.y)};
            #pragma unroll
            for (int nt = 0; nt < 8; nt++) {
                int dn = dh0 + nt * 8 + gid;
                float2 b0 = V2[(tk  )*KS2 + dn];
                float2 b1 = V2[(tk+4)*KS2 + dn];
                mma_tf32(o[nt], ah, f2u(b0.x), f2u(b1.x));
                mma_tf32(o[nt], al, f2u(b0.x), f2u(b1.x));
                mma_tf32(o[nt], ah, f2u(b0.y), f2u(b1.y));
            }
        }
    }

    // ---- combine p-max across token-half warps ----
    #pragma unroll
    for (int off = 1; off < 4; off <<= 1) {
        pmax0 = fmaxf(pmax0, __shfl_xor_sync(0xffffffffu, pmax0, off));
        pmax1 = fmaxf(pmax1, __shfl_xor_sync(0xffffffffu, pmax1, off));
    }
    if (tig == 0) {
        PM[wh * 64 + qb + gid    ] = pmax0;
        PM[wh * 64 + qb + gid + 8] = pmax1;
    }
    __syncthreads();
    float pm0 = fmaxf(PM[qb + gid    ], PM[64 + qb + gid    ]);
    float pm1 = fmaxf(PM[qb + gid + 8], PM[64 + qb + gid + 8]);
    const float f0 = (pm0 > 0.f) ? (1.0f / pm0) : 0.f;
    const float f1 = (pm1 > 0.f) ? (1.0f / pm1) : 0.f;

    // ---- write out[t][h][seg][d] ----
    const int trow0 = s * QLEN + qh * 64 + qb + gid;
    float* o0 = out + (((size_t)trow0       * NQH + h) * NSEG + seg) * (size_t)HD + dh0;
    float* o1 = out + (((size_t)(trow0 + 8) * NQH + h) * NSEG + seg) * (size_t)HD + dh0;
    #pragma unroll
    for (int nt = 0; nt < 8; nt++) {
        int d0 = nt * 8 + 2 * tig;
        *(float2*)(o0 + d0) = make_float2(o[nt][0] * f0, o[nt][1] * f0);
        *(float2*)(o1 + d0) = make_float2(o[nt][2] * f1, o[nt][3] * f1);
    }
}

extern "C" void kernel_launch(void* const* d_in, const int* in_sizes, int n_in,
                              void* d_out, int out_size) {
    const float* q   = (const float*)d_in[0];
    const float* kc  = (const float*)d_in[1];
    const float* vc  = (const float*)d_in[2];
    const int*   bt  = (const int*)d_in[3];
    const int*   sl  = (const int*)d_in[4];
    const float* sc  = (const float*)d_in[6];
    const float* cap = (const float*)d_in[9];
    float* out = (float*)d_out;

    static int init_done = 0;
    if (!init_done) {
        cudaFuncSetAttribute(paged_seg_attn_mma8,
                             cudaFuncAttributeMaxDynamicSharedMemorySize, SMEM_BYTES);
        init_done = 1;
    }
    dim3 grid(NSEG * 2, GQA, NSEQ * NKVH);
    paged_seg_attn_mma8<<<grid, NTHREADS, SMEM_BYTES>>>(q, kc, vc, bt, sl, sc, cap, out);
}

// round 8
// speedup vs baseline: 2.6260x; 2.0741x over previous
#include <cuda_runtime.h>
#include <cstdint>

#define NSEQ 8
#define QLEN 128
#define NQH 32
#define NKVH 8
#define GQA 4
#define HD 128
#define BLKSZ 16
#define MAXBLK 128
#define LTOT 2048
#define NSEG 4
#define TILEC 32

#define NCT 64
#define NTHREADS 256

// u32-word offsets in dynamic smem
// Q32h/Q32l: [64 rows][68]   (d-pair major, pad 4 -> bank 4*row)
// K32h/K32l: [64 dpair][68]  (tok major)
// V32h/V32l: [128 d][36]     (tok-pair major, pad 4)
// P32h/P32l: overlay K region, [64 rows][36]
#define QS 68
#define KS 68
#define VS 36
#define PS 36
#define OFF_QH 0
#define OFF_QL (OFF_QH + 64*QS)
#define OFF_KH (OFF_QL + 64*QS)
#define OFF_KL (OFF_KH + 64*KS)
#define OFF_VH (OFF_KL + 64*KS)
#define OFF_VL (OFF_VH + 128*VS)
#define OFF_PM (OFF_VL + 128*VS)
#define OFF_PH OFF_KH
#define OFF_PL (OFF_KH + 64*PS)
#define SMEM_U32 (OFF_PM + 128)
#define SMEM_BYTES (SMEM_U32*4)

static __device__ __forceinline__ void mma_bf16(float c[4], const uint32_t a[4],
                                                uint32_t b0, uint32_t b1) {
    asm volatile(
        "mma.sync.aligned.m16n8k16.row.col.f32.bf16.bf16.f32 "
        "{%0,%1,%2,%3}, {%4,%5,%6,%7}, {%8,%9}, {%0,%1,%2,%3};"
        : "+f"(c[0]), "+f"(c[1]), "+f"(c[2]), "+f"(c[3])
        : "r"(a[0]), "r"(a[1]), "r"(a[2]), "r"(a[3]), "r"(b0), "r"(b1));
}

// pack two floats into bf16x2: element0(low)=x0, element1(high)=x1
static __device__ __forceinline__ uint32_t pkbf2(float x0, float x1) {
    uint32_t r;
    asm("cvt.rn.bf16x2.f32 %0, %1, %2;" : "=r"(r) : "f"(x1), "f"(x0));
    return r;
}
// hi/lo split of a pair: hp = bf16x2(hi), lp = bf16x2(residual)
static __device__ __forceinline__ void split2(float x0, float x1,
                                              uint32_t& hp, uint32_t& lp) {
    hp = pkbf2(x0, x1);
    float h0 = __uint_as_float(hp << 16);
    float h1 = __uint_as_float(hp & 0xffff0000u);
    lp = pkbf2(x0 - h0, x1 - h1);
}

__global__ void __launch_bounds__(NTHREADS, 2)
paged_seg_attn_bf3(const float* __restrict__ q,
                   const float* __restrict__ kc,
                   const float* __restrict__ vc,
                   const int*   __restrict__ bt,
                   const int*   __restrict__ seqlens,
                   const float* __restrict__ scale_p,
                   const float* __restrict__ softcap_p,
                   float*       __restrict__ out)
{
    extern __shared__ uint32_t smw[];
    uint32_t* Qh = smw + OFF_QH;
    uint32_t* Ql = smw + OFF_QL;
    uint32_t* Kh = smw + OFF_KH;
    uint32_t* Kl = smw + OFF_KL;
    uint32_t* Vh = smw + OFF_VH;
    uint32_t* Vl = smw + OFF_VL;
    uint32_t* Ph = smw + OFF_PH;
    uint32_t* Pl = smw + OFF_PL;
    float*    PM = (float*)(smw + OFF_PM);

    const int bx  = blockIdx.x;      // seg*2 + qhalf
    const int seg = bx >> 1;
    const int qh  = bx & 1;
    const int g   = blockIdx.y;
    const int z   = blockIdx.z;
    const int s   = z >> 3;
    const int kv  = z & 7;
    const int h   = kv * GQA + g;

    const int tid  = threadIdx.x;
    const int w    = tid >> 5;
    const int wq   = w >> 1;         // q rows wq*16..+15
    const int wh   = w & 1;          // QK token half / PV d half
    const int lane = tid & 31;
    const int gid  = lane >> 2;
    const int tig  = lane & 3;
    const int qb   = wq * 16;
    const int th0  = wh * 32;
    const int dh0  = wh * 64;

    const float scale = *scale_p;
    const float cap   = *softcap_p;
    const float tcoef = (cap > 0.f) ? (2.0f * scale / cap) : 0.f;
    const float n2cap = -2.0f * cap;

    const int seq_len   = seqlens[s];
    const int ctx       = seq_len - QLEN;
    const int span      = ((seq_len + NSEG * TILEC - 1) / (NSEG * TILEC)) * TILEC;
    const int seg_start = seg * span;
    const int seg_end   = min(seg_start + span, LTOT);

    const int kmax0 = ctx + qh * 64 + qb + gid;
    const int kmax1 = kmax0 + 8;

    const int* btrow = bt + s * MAXBLK;

    // ---- stage Q once: hi/lo bf16x2, [row][d-pair] ----
    #pragma unroll
    for (int it = 0; it < 8; it++) {
        int i  = tid + it * NTHREADS;            // 0..2047
        int r  = i >> 5;                         // 0..63
        int d4 = (i & 31) * 4;
        const float* src = q + ((size_t)(s * QLEN + qh * 64 + r) * NQH + h) * HD + d4;
        float4 v = *(const float4*)src;
        uint32_t h01, l01, h23, l23;
        split2(v.x, v.y, h01, l01);
        split2(v.z, v.w, h23, l23);
        int o2 = r * QS + (d4 >> 1);
        *(uint2*)(Qh + o2) = make_uint2(h01, h23);
        *(uint2*)(Ql + o2) = make_uint2(l01, l23);
    }

    float o[8][4];
    #pragma unroll
    for (int a = 0; a < 8; a++)
        #pragma unroll
        for (int b = 0; b < 4; b++) o[a][b] = 0.f;

    float pmax0 = 0.f, pmax1 = 0.f;

    for (int base = seg_start; base < seg_end; base += NCT) {
        __syncthreads();   // prev chunk fully consumed

        // ---- stage K: [d-pair][tok]; thread: one d-pair, 4 toks ----
        #pragma unroll
        for (int it = 0; it < 4; it++) {
            int i   = tid + it * NTHREADS;       // 0..1023
            int d2  = i >> 4;                    // 0..63
            int tq  = i & 15;
            int t0  = tq * 4;
            int pb  = btrow[(base >> 4) + (t0 >> 4)];
            const float* kb0 = kc + (((size_t)pb * NKVH + kv) * HD + 2*d2) * BLKSZ + (t0 & 15);
            float4 va = *(const float4*)(kb0);          // d=2*d2, toks t0..t0+3
            float4 vb = *(const float4*)(kb0 + BLKSZ);  // d=2*d2+1
            float ea[4] = {va.x, va.y, va.z, va.w};
            float eb[4] = {vb.x, vb.y, vb.z, vb.w};
            #pragma unroll
            for (int j = 0; j < 4; j++) {
                uint32_t hp, lp;
                split2(ea[j], eb[j], hp, lp);
                Kh[d2 * KS + t0 + j] = hp;
                Kl[d2 * KS + t0 + j] = lp;
            }
        }
        // ---- stage V: [d][tok-pair]; thread: one d, 8 toks ----
        #pragma unroll
        for (int it = 0; it < 4; it++) {
            int i   = tid + it * NTHREADS;       // 0..1023
            int d   = i >> 3;                    // 0..127
            int th  = i & 7;
            int t0  = th * 8;
            int pb  = btrow[(base >> 4) + (th >> 1)];
            const float* vb0 = vc + (((size_t)pb * NKVH + kv) * HD + d) * BLKSZ + ((th & 1) * 8);
            float4 va = *(const float4*)(vb0);
            float4 vb = *(const float4*)(vb0 + 4);
            uint4 hv, lv;
            split2(va.x, va.y, hv.x, lv.x);
            split2(va.z, va.w, hv.y, lv.y);
            split2(vb.x, vb.y, hv.z, lv.z);
            split2(vb.z, vb.w, hv.w, lv.w);
            int o2 = d * VS + (t0 >> 1);
            *(uint4*)(Vh + o2) = hv;
            *(uint4*)(Vl + o2) = lv;
        }
        __syncthreads();

        // ---- QK: 16q x 32tok per warp, K=128 (8 k16 steps), 3-term bf16 ----
        float sacc[4][4];
        #pragma unroll
        for (int a = 0; a < 4; a++)
            #pragma unroll
            for (int b = 0; b < 4; b++) sacc[a][b] = 0.f;

        #pragma unroll
        for (int ks = 0; ks < 8; ks++) {
            int ca = ks * 8 + tig;
            uint32_t ah[4], al[4];
            ah[0] = Qh[(qb+gid  )*QS + ca];
            ah[1] = Qh[(qb+gid+8)*QS + ca];
            ah[2] = Qh[(qb+gid  )*QS + ca + 4];
            ah[3] = Qh[(qb+gid+8)*QS + ca + 4];
            al[0] = Ql[(qb+gid  )*QS + ca];
            al[1] = Ql[(qb+gid+8)*QS + ca];
            al[2] = Ql[(qb+gid  )*QS + ca + 4];
            al[3] = Ql[(qb+gid+8)*QS + ca + 4];
            #pragma unroll
            for (int nt = 0; nt < 4; nt++) {
                int tn = th0 + nt * 8 + gid;
                uint32_t bh0 = Kh[(ks*8 + tig    )*KS + tn];
                uint32_t bh1 = Kh[(ks*8 + tig + 4)*KS + tn];
                uint32_t bl0 = Kl[(ks*8 + tig    )*KS + tn];
                uint32_t bl1 = Kl[(ks*8 + tig + 4)*KS + tn];
                mma_bf16(sacc[nt], ah, bh0, bh1);
                mma_bf16(sacc[nt], al, bh0, bh1);
                mma_bf16(sacc[nt], ah, bl0, bl1);
            }
        }

        // ---- softcap + mask + p = exp(v - cap) ----
        uint32_t pph[4][2], ppl[4][2];   // [nt][row0/row1] packed tok-pairs
        #pragma unroll
        for (int nt = 0; nt < 4; nt++) {
            float pe[4];
            #pragma unroll
            for (int e = 0; e < 4; e++) {
                int tpos = base + th0 + nt * 8 + 2 * tig + (e & 1);
                int kmax = (e < 2) ? kmax0 : kmax1;
                float raw = sacc[nt][e];
                float ex  = __expf(raw * tcoef);
                float p   = __expf(__fdividef(n2cap, ex + 1.f));   // exp(v - cap)
                bool ok   = (tpos <= kmax) && (tpos < seg_end);
                p = ok ? p : 0.f;
                if (e < 2) pmax0 = fmaxf(pmax0, p); else pmax1 = fmaxf(pmax1, p);
                pe[e] = p;
            }
            split2(pe[0], pe[1], pph[nt][0], ppl[nt][0]);
            split2(pe[2], pe[3], pph[nt][1], ppl[nt][1]);
        }

        __syncthreads();   // all QK reads of K done -> overlay P

        // ---- store P: [row][tok-pair] ----
        #pragma unroll
        for (int nt = 0; nt < 4; nt++) {
            int tp = (th0 >> 1) + nt * 4 + tig;
            Ph[(qb+gid  )*PS + tp] = pph[nt][0];
            Ph[(qb+gid+8)*PS + tp] = pph[nt][1];
            Pl[(qb+gid  )*PS + tp] = ppl[nt][0];
            Pl[(qb+gid+8)*PS + tp] = ppl[nt][1];
        }
        __syncthreads();

        // ---- PV: 16q x 64d per warp, K=64 toks (4 k16 steps) ----
        #pragma unroll
        for (int ks = 0; ks < 4; ks++) {
            int ca = ks * 8 + tig;
            uint32_t ah[4], al[4];
            ah[0] = Ph[(qb+gid  )*PS + ca];
            ah[1] = Ph[(qb+gid+8)*PS + ca];
            ah[2] = Ph[(qb+gid  )*PS + ca + 4];
            ah[3] = Ph[(qb+gid+8)*PS + ca + 4];
            al[0] = Pl[(qb+gid  )*PS + ca];
            al[1] = Pl[(qb+gid+8)*PS + ca];
            al[2] = Pl[(qb+gid  )*PS + ca + 4];
            al[3] = Pl[(qb+gid+8)*PS + ca + 4];
            #pragma unroll
            for (int nt = 0; nt < 8; nt++) {
                int dn = dh0 + nt * 8 + gid;
                uint32_t bh0 = Vh[dn*VS + ca];
                uint32_t bh1 = Vh[dn*VS + ca + 4];
                uint32_t bl0 = Vl[dn*VS + ca];
                uint32_t bl1 = Vl[dn*VS + ca + 4];
                mma_bf16(o[nt], ah, bh0, bh1);
                mma_bf16(o[nt], al, bh0, bh1);
                mma_bf16(o[nt], ah, bl0, bl1);
            }
        }
    }

    // ---- combine p-max across lanes + token-half warps ----
    #pragma unroll
    for (int off = 1; off < 4; off <<= 1) {
        pmax0 = fmaxf(pmax0, __shfl_xor_sync(0xffffffffu, pmax0, off));
        pmax1 = fmaxf(pmax1, __shfl_xor_sync(0xffffffffu, pmax1, off));
    }
    if (tig == 0) {
        PM[wh * 64 + qb + gid    ] = pmax0;
        PM[wh * 64 + qb + gid + 8] = pmax1;
    }
    __syncthreads();
    float pm0 = fmaxf(PM[qb + gid    ], PM[64 + qb + gid    ]);
    float pm1 = fmaxf(PM[qb + gid + 8], PM[64 + qb + gid + 8]);
    const float f0 = (pm0 > 0.f) ? (1.0f / pm0) : 0.f;
    const float f1 = (pm1 > 0.f) ? (1.0f / pm1) : 0.f;

    // ---- write out[t][h][seg][d] ----
    const int trow0 = s * QLEN + qh * 64 + qb + gid;
    float* o0 = out + (((size_t)trow0       * NQH + h) * NSEG + seg) * (size_t)HD + dh0;
    float* o1 = out + (((size_t)(trow0 + 8) * NQH + h) * NSEG + seg) * (size_t)HD + dh0;
    #pragma unroll
    for (int nt = 0; nt < 8; nt++) {
        int d0 = nt * 8 + 2 * tig;
        *(float2*)(o0 + d0) = make_float2(o[nt][0] * f0, o[nt][1] * f0);
        *(float2*)(o1 + d0) = make_float2(o[nt][2] * f1, o[nt][3] * f1);
    }
}

extern "C" void kernel_launch(void* const* d_in, const int* in_sizes, int n_in,
                              void* d_out, int out_size) {
    const float* q   = (const float*)d_in[0];
    const float* kc  = (const float*)d_in[1];
    const float* vc  = (const float*)d_in[2];
    const int*   bt  = (const int*)d_in[3];
    const int*   sl  = (const int*)d_in[4];
    const float* sc  = (const float*)d_in[6];
    const float* cap = (const float*)d_in[9];
    float* out = (float*)d_out;

    static int init_done = 0;
    if (!init_done) {
        cudaFuncSetAttribute(paged_seg_attn_bf3,
                             cudaFuncAttributeMaxDynamicSharedMemorySize, SMEM_BYTES);
        init_done = 1;
    }
    dim3 grid(NSEG * 2, GQA, NSEQ * NKVH);
    paged_seg_attn_bf3<<<grid, NTHREADS, SMEM_BYTES>>>(q, kc, vc, bt, sl, sc, cap, out);
}